// round 2
// baseline (speedup 1.0000x reference)
#include <cuda_runtime.h>

// VectorQuantizer forward:
//   out  = x  (reference's original "bug": returns rearranged input == x)
//   loss = 1.25/(N*E) * ( sum(x^2) + sum_n min_k( ||e_k||^2 - 2 x_n . e_k ) )
// N = 32*32*32 = 32768 vectors, E = 256, K = 1024 codes.
// x layout is [B=32, C=256, H=32, W=32]; vector n=(b,h,w) has elements at
// stride H*W=1024 in c.  codebook is [K, E] row-major.

#define NVEC   32768
#define EDIM   256
#define KCODE  1024
#define TM     64     // rows (n) per block
#define TK     64     // codes per k-chunk
#define DC     16     // embed-dim slice per smem stage

__device__ double g_sumx2;
__device__ double g_summin;
__device__ float  g_enorm2[KCODE];

__global__ void init_kernel() {
    g_sumx2 = 0.0;
    g_summin = 0.0;
}

// ||e_k||^2 for each code, one warp per code.
__global__ void enorm_kernel(const float* __restrict__ cb) {
    int k = blockIdx.x;
    int lane = threadIdx.x;                       // 32 lanes
    const float4* row = (const float4*)(cb + (size_t)k * EDIM);
    float s = 0.f;
#pragma unroll
    for (int i = 0; i < 2; ++i) {
        float4 v = row[lane + 32 * i];
        s += v.x * v.x + v.y * v.y + v.z * v.z + v.w * v.w;
    }
#pragma unroll
    for (int o = 16; o; o >>= 1) s += __shfl_xor_sync(0xffffffffu, s, o);
    if (lane == 0) g_enorm2[k] = s;
}

// sum(x^2) over all elements (layout-independent).
__global__ void sumx2_kernel(const float* __restrict__ x, int n4) {
    int tid = blockIdx.x * blockDim.x + threadIdx.x;
    int stride = gridDim.x * blockDim.x;
    const float4* x4 = (const float4*)x;
    float s = 0.f;
    for (int i = tid; i < n4; i += stride) {
        float4 v = x4[i];
        s += v.x * v.x + v.y * v.y + v.z * v.z + v.w * v.w;
    }
#pragma unroll
    for (int o = 16; o; o >>= 1) s += __shfl_xor_sync(0xffffffffu, s, o);
    __shared__ float ws[8];
    if ((threadIdx.x & 31) == 0) ws[threadIdx.x >> 5] = s;
    __syncthreads();
    if (threadIdx.x < 8) {
        float v = ws[threadIdx.x];
#pragma unroll
        for (int o = 4; o; o >>= 1) v += __shfl_xor_sync(0xffu, v, o);
        if (threadIdx.x == 0) atomicAdd(&g_sumx2, (double)v);
    }
}

// Fused GEMM + per-row min.  One block handles TM=64 rows against all K codes,
// looping codes in TK=64 chunks; each chunk accumulates the full E=256 dot
// product through DC=16-wide smem stages, then folds into a running row-min.
__global__ __launch_bounds__(256) void vq_min_kernel(const float* __restrict__ x,
                                                     const float* __restrict__ cb) {
    __shared__ float xs[DC][TM];
    __shared__ float es[DC][TK + 4];   // pad to 68 floats to cut store conflicts

    int tid = threadIdx.x;
    int tx = tid & 15;        // code sub-tile (4 codes)
    int ty = tid >> 4;        // row sub-tile  (4 rows)

    int n0  = blockIdx.x * TM;
    int b   = n0 >> 10;                 // 1024 vectors per batch image
    int nhw = n0 & 1023;
    const float* xbase = x + (size_t)b * (EDIM * 1024) + nhw;

    // loader roles
    int ldc = tid >> 4;        // 0..15 : d within stage (x loader)
    int lm4 = (tid & 15) * 4;  // row offset (x loader, float4)
    int lk  = tid >> 2;        // 0..63 : code within chunk (e loader)
    int ldv = (tid & 3) * 4;   // d offset (e loader, float4)

    float rowmin[4] = {1e30f, 1e30f, 1e30f, 1e30f};

    for (int kc = 0; kc < KCODE / TK; ++kc) {
        int k0 = kc * TK;
        float acc[4][4];
#pragma unroll
        for (int i = 0; i < 4; ++i)
#pragma unroll
            for (int j = 0; j < 4; ++j) acc[i][j] = 0.f;

        for (int dcb = 0; dcb < EDIM / DC; ++dcb) {
            int c0 = dcb * DC;
            __syncthreads();   // previous stage fully consumed
            // x tile: xs[d][m] = x[b, c0+d, nhw+m]   (coalesced over m)
            float4 xv = *(const float4*)(xbase + (size_t)(c0 + ldc) * 1024 + lm4);
            *(float4*)&xs[ldc][lm4] = xv;
            // e tile (transposed store): es[d][k] = cb[k0+k, c0+d]
            float4 ev = *(const float4*)(cb + (size_t)(k0 + lk) * EDIM + c0 + ldv);
            es[ldv + 0][lk] = ev.x;
            es[ldv + 1][lk] = ev.y;
            es[ldv + 2][lk] = ev.z;
            es[ldv + 3][lk] = ev.w;
            __syncthreads();
#pragma unroll
            for (int d = 0; d < DC; ++d) {
                float4 a  = *(const float4*)&xs[d][ty * 4];
                float4 bb = *(const float4*)&es[d][tx * 4];
                float av[4] = {a.x, a.y, a.z, a.w};
                float bv[4] = {bb.x, bb.y, bb.z, bb.w};
#pragma unroll
                for (int i = 0; i < 4; ++i)
#pragma unroll
                    for (int j = 0; j < 4; ++j)
                        acc[i][j] += av[i] * bv[j];
            }
        }
        // fold chunk into running row-min: s = ||e||^2 - 2 x.e
#pragma unroll
        for (int j = 0; j < 4; ++j) {
            float en = g_enorm2[k0 + tx * 4 + j];
#pragma unroll
            for (int i = 0; i < 4; ++i) {
                float s = en - 2.f * acc[i][j];
                rowmin[i] = fminf(rowmin[i], s);
            }
        }
    }

    // min over the 16 tx lanes sharing the same rows (xor offsets stay in half-warp)
#pragma unroll
    for (int i = 0; i < 4; ++i) {
        float v = rowmin[i];
#pragma unroll
        for (int o = 8; o; o >>= 1) v = fminf(v, __shfl_xor_sync(0xffffffffu, v, o));
        rowmin[i] = v;
    }

    __shared__ float bsum[16];
    if (tx == 0) bsum[ty] = rowmin[0] + rowmin[1] + rowmin[2] + rowmin[3];
    __syncthreads();
    if (tid < 16) {
        float v = bsum[tid];
#pragma unroll
        for (int o = 8; o; o >>= 1) v += __shfl_xor_sync(0xffffu, v, o);
        if (tid == 0) atomicAdd(&g_summin, (double)v);
    }
}

__global__ void finalize_kernel(float* __restrict__ out, long long loss_idx) {
    double mean = (g_sumx2 + g_summin) / (double)((long long)NVEC * EDIM);
    out[loss_idx] = (float)(1.25 * mean);   // (1 + BETA) * mean
}

extern "C" void kernel_launch(void* const* d_in, const int* in_sizes, int n_in,
                              void* d_out, int out_size) {
    (void)n_in;
    const float* x  = (const float*)d_in[0];
    const float* cb = (const float*)d_in[1];
    float* out = (float*)d_out;

    init_kernel<<<1, 1>>>();
    enorm_kernel<<<KCODE, 32>>>(cb);
    sumx2_kernel<<<1024, 256>>>(x, NVEC * EDIM / 4);
    vq_min_kernel<<<NVEC / TM, 256>>>(x, cb);

    // out = x (the reference returns the rearranged input, which is x exactly)
    long long ncopy = (long long)in_sizes[0];
    if ((long long)out_size - 1 < ncopy) ncopy = (long long)out_size - 1;
    cudaMemcpyAsync(out, x, (size_t)ncopy * sizeof(float),
                    cudaMemcpyDeviceToDevice);

    finalize_kernel<<<1, 1>>>(out, (long long)out_size - 1);
}

// round 5
// speedup vs baseline: 6.7213x; 6.7213x over previous
#include <cuda_runtime.h>
#include <cuda_bf16.h>
#include <cstdint>

// VectorQuantizer forward (GB300, baseline-PTX tensor cores: mma.sync bf16):
//   out  = x  (reference returns the rearranged input == x bit-exactly)
//   loss = 1.25/(N*E) * ( sum(x^2) + sum_n min_k( ||e_k||^2 - 2 x_n . e_k ) )
// N=32768, E=256, K=1024.  x: [32,256,32,32] (vector n=(b,hw), dim stride 1024).
// codebook: [1024,256] f32 row-major.  GEMM in bf16 HMMA w/ fp32 accum.

#define NVEC  32768
#define EDIM  256
#define KCODE 1024

#define CTA_M 128
#define CTA_N 128          // codes per chunk
#define NCH   (KCODE/CTA_N)   // 8
#define KTILE 32           // k per B tile
#define NKT   (EDIM/KTILE)    // 8

// smem layout (bytes).  A row = 256 bf16 + 8 pad = 528 B (16B aligned).
#define AROW   528
#define SM_A   0                         // 128*528 = 67584
#define BROW   80                        // 32 bf16 + 8 pad
#define SM_B0  67584                     // 128*80 = 10240
#define SM_B1  77824
#define SM_EN  88064                     // 1024 f32 = 4096
#define SM_RM  92160                     // 4*128 f32 = 2048
#define SM_XS  67584                     // f32 staging [64][128] = 32768 (overlaps B/EN/RM, used before them)
#define SMEM_TOTAL 100352

__device__ double g_sumx2;
__device__ double g_summin;
__device__ float  g_enorm2[KCODE];
__device__ __nv_bfloat16 g_cbb[(size_t)KCODE * EDIM];

// ---------------- PTX helpers ----------------
__device__ __forceinline__ uint32_t smem_u32(const void* p) {
    uint32_t a;
    asm("{ .reg .u64 t; cvta.to.shared.u64 t, %1; cvt.u32.u64 %0, t; }"
        : "=r"(a) : "l"(p));
    return a;
}
__device__ __forceinline__ uint32_t pack_bf16x2(float lo, float hi) {
    uint32_t r;
    asm("cvt.rn.bf16x2.f32 %0, %1, %2;" : "=r"(r) : "f"(hi), "f"(lo));
    return r;
}
__device__ __forceinline__ void ldsm_x4(uint32_t* r, uint32_t addr) {
    asm volatile("ldmatrix.sync.aligned.m8n8.x4.shared.b16 {%0,%1,%2,%3}, [%4];"
                 : "=r"(r[0]), "=r"(r[1]), "=r"(r[2]), "=r"(r[3]) : "r"(addr));
}
__device__ __forceinline__ void ldsm_x4t(uint32_t* r, uint32_t addr) {
    asm volatile("ldmatrix.sync.aligned.m8n8.x4.trans.shared.b16 {%0,%1,%2,%3}, [%4];"
                 : "=r"(r[0]), "=r"(r[1]), "=r"(r[2]), "=r"(r[3]) : "r"(addr));
}
__device__ __forceinline__ void mma16816(float* d, const uint32_t* a, const uint32_t* b) {
    asm volatile(
        "mma.sync.aligned.m16n8k16.row.col.f32.bf16.bf16.f32 "
        "{%0,%1,%2,%3}, {%4,%5,%6,%7}, {%8,%9}, {%0,%1,%2,%3};"
        : "+f"(d[0]), "+f"(d[1]), "+f"(d[2]), "+f"(d[3])
        : "r"(a[0]), "r"(a[1]), "r"(a[2]), "r"(a[3]), "r"(b[0]), "r"(b[1]));
}
#define CP_ASYNC16(s, g) \
    asm volatile("cp.async.cg.shared.global [%0], [%1], 16;" :: "r"(s), "l"(g))
#define CP_COMMIT() asm volatile("cp.async.commit_group;" ::: "memory")
#define CP_WAIT1()  asm volatile("cp.async.wait_group 1;" ::: "memory")
#define CP_WAIT0()  asm volatile("cp.async.wait_group 0;" ::: "memory")

// ---------------- small kernels ----------------
__global__ void init_kernel() { g_sumx2 = 0.0; g_summin = 0.0; }

__global__ void enorm_kernel(const float* __restrict__ cb) {
    int k = blockIdx.x, lane = threadIdx.x;
    const float4* row = (const float4*)(cb + (size_t)k * EDIM);
    float s = 0.f;
#pragma unroll
    for (int i = 0; i < 2; ++i) {
        float4 v = row[lane + 32 * i];
        s += v.x * v.x + v.y * v.y + v.z * v.z + v.w * v.w;
    }
#pragma unroll
    for (int o = 16; o; o >>= 1) s += __shfl_xor_sync(0xffffffffu, s, o);
    if (lane == 0) g_enorm2[k] = s;
}

__global__ void cbconv_kernel(const float* __restrict__ cb) {
    int i = blockIdx.x * blockDim.x + threadIdx.x;
    float4 v = ((const float4*)cb)[i];
    uint2 p;
    p.x = pack_bf16x2(v.x, v.y);
    p.y = pack_bf16x2(v.z, v.w);
    ((uint2*)g_cbb)[i] = p;
}

// ---------------- fused HMMA GEMM + row-min + sum(x^2) ----------------
extern __shared__ __align__(1024) unsigned char smem[];

__global__ __launch_bounds__(256, 2) void vq_mma_kernel(const float* __restrict__ x) {
    uint32_t sb = smem_u32(smem);
    int tid = threadIdx.x;
    int wid = tid >> 5, lane = tid & 31;
    int wm = wid >> 2, wn = wid & 3;          // warp tile: rows wm*64, cols wn*32

    // ---- Phase 1: build A (bf16 [128 rows][256 dims]) in smem; fold sum(x^2) ----
    int n0 = blockIdx.x * CTA_M;
    int b = n0 >> 10, hw0 = n0 & 1023;
    const float* xb = x + (size_t)b * (EDIM * 1024) + hw0;
    float* xs = (float*)(smem + SM_XS);
    float sq = 0.f;
    int row128 = tid & 127, chalf = tid >> 7;
#pragma unroll 1
    for (int q = 0; q < 4; ++q) {            // 64 dims per stage
        __syncthreads();
#pragma unroll
        for (int it = 0; it < 8; ++it) {
            int i = tid + it * 256;          // 0..2047 float4 slots
            int c = i >> 5, m4 = (i & 31) * 4;
            float4 v = *(const float4*)(xb + (size_t)(q * 64 + c) * 1024 + m4);
            *(float4*)(xs + c * 128 + m4) = v;
            sq += v.x * v.x + v.y * v.y + v.z * v.z + v.w * v.w;
        }
        __syncthreads();
        // pack: thread owns row row128, dims [chalf*32 .. +32) of this stage
#pragma unroll
        for (int j = 0; j < 4; ++j) {        // 8 dims -> one 16B store
            int cl = chalf * 32 + j * 8;
            uint4 w;
            w.x = pack_bf16x2(xs[(cl + 0) * 128 + row128], xs[(cl + 1) * 128 + row128]);
            w.y = pack_bf16x2(xs[(cl + 2) * 128 + row128], xs[(cl + 3) * 128 + row128]);
            w.z = pack_bf16x2(xs[(cl + 4) * 128 + row128], xs[(cl + 5) * 128 + row128]);
            w.w = pack_bf16x2(xs[(cl + 6) * 128 + row128], xs[(cl + 7) * 128 + row128]);
            *(uint4*)(smem + SM_A + row128 * AROW + q * 128 + chalf * 64 + j * 16) = w;
        }
    }
    __syncthreads();

    // ---- Phase 2: enorm -> smem ----
    {
        float4 e = ((const float4*)g_enorm2)[tid];
        *(float4*)(smem + SM_EN + tid * 16) = e;
    }

    // ---- Phase 3: main loop, cp.async double-buffered B ----
    // B tile t (nc=t>>3, kk=t&7): 128 codes x 32 dims bf16, row stride 80B.
    {
        int i0 = tid, i1 = tid + 256;        // 512 x 16B per tile
        int r0 = i0 >> 2, s0 = i0 & 3, r1 = i1 >> 2, s1 = i1 & 3;
        const __nv_bfloat16* src = g_cbb;    // t=0
        CP_ASYNC16(sb + SM_B0 + r0 * BROW + s0 * 16, src + r0 * 256 + s0 * 8);
        CP_ASYNC16(sb + SM_B0 + r1 * BROW + s1 * 16, src + r1 * 256 + s1 * 8);
        CP_COMMIT();
    }

    // per-lane ldmatrix base addresses
    uint32_t a_base = sb + SM_A + (uint32_t)(wm * 64 + (lane & 15)) * AROW
                    + (uint32_t)(lane >> 4) * 16;
    uint32_t b_lrow = (uint32_t)(wn * 32 + (lane & 7) + ((lane >> 4) & 1) * 8);
    uint32_t b_off  = b_lrow * BROW + (uint32_t)((lane >> 3) & 1) * 16;

    float regmin[8];
#pragma unroll
    for (int i = 0; i < 8; ++i) regmin[i] = 3.0e38f;

#pragma unroll 1
    for (int nc = 0; nc < NCH; ++nc) {
        float acc[4][4][4];
#pragma unroll
        for (int mi = 0; mi < 4; ++mi)
#pragma unroll
            for (int nj = 0; nj < 4; ++nj)
#pragma unroll
                for (int c = 0; c < 4; ++c) acc[mi][nj][c] = 0.f;

#pragma unroll 1
        for (int kk = 0; kk < NKT; ++kk) {
            int t = nc * NKT + kk;
            if (t + 1 < NCH * NKT) {
                int tn = t + 1;
                uint32_t dstb = sb + (((tn) & 1) ? SM_B1 : SM_B0);
                const __nv_bfloat16* src = g_cbb
                    + (size_t)(tn >> 3) * CTA_N * EDIM + (tn & 7) * KTILE;
                int i0 = tid, i1 = tid + 256;
                int r0 = i0 >> 2, s0 = i0 & 3, r1 = i1 >> 2, s1 = i1 & 3;
                CP_ASYNC16(dstb + r0 * BROW + s0 * 16, src + r0 * 256 + s0 * 8);
                CP_ASYNC16(dstb + r1 * BROW + s1 * 16, src + r1 * 256 + s1 * 8);
                CP_COMMIT();
                CP_WAIT1();
            } else {
                CP_WAIT0();
            }
            __syncthreads();

            uint32_t bbase = sb + ((t & 1) ? SM_B1 : SM_B0) + b_off;
            uint32_t abase = a_base + (uint32_t)kk * 64;
#pragma unroll
            for (int kq = 0; kq < 2; ++kq) {
                uint32_t af[4][4], bf[2][4];
#pragma unroll
                for (int mi = 0; mi < 4; ++mi)
                    ldsm_x4(af[mi], abase + (uint32_t)(mi * 16) * AROW + kq * 32);
#pragma unroll
                for (int nh = 0; nh < 2; ++nh)
                    ldsm_x4t(bf[nh], bbase + (uint32_t)(nh * 16) * BROW + kq * 32);
#pragma unroll
                for (int mi = 0; mi < 4; ++mi) {
#pragma unroll
                    for (int nh = 0; nh < 2; ++nh) {
                        mma16816(acc[mi][nh * 2 + 0], af[mi], &bf[nh][0]);
                        mma16816(acc[mi][nh * 2 + 1], af[mi], &bf[nh][2]);
                    }
                }
            }
            __syncthreads();   // all warps done with this B buffer
        }

        // ---- epilogue: fold en[k] - 2*dot into per-lane row minima ----
        const float* en = (const float*)(smem + SM_EN) + nc * 128;
#pragma unroll
        for (int nj = 0; nj < 4; ++nj) {
            int col = wn * 32 + nj * 8 + (lane & 3) * 2;
            float e0 = en[col], e1 = en[col + 1];
#pragma unroll
            for (int mi = 0; mi < 4; ++mi) {
                float s0 = fmaf(acc[mi][nj][0], -2.f, e0);
                float s1 = fmaf(acc[mi][nj][1], -2.f, e1);
                float s2 = fmaf(acc[mi][nj][2], -2.f, e0);
                float s3 = fmaf(acc[mi][nj][3], -2.f, e1);
                regmin[mi * 2 + 0] = fminf(regmin[mi * 2 + 0], fminf(s0, s1));
                regmin[mi * 2 + 1] = fminf(regmin[mi * 2 + 1], fminf(s2, s3));
            }
        }
    }

    // ---- Phase 4: reductions ----
    // min across the 4 lanes sharing each row (lane&3 varies)
#pragma unroll
    for (int i = 0; i < 8; ++i) {
        regmin[i] = fminf(regmin[i], __shfl_xor_sync(0xffffffffu, regmin[i], 1));
        regmin[i] = fminf(regmin[i], __shfl_xor_sync(0xffffffffu, regmin[i], 2));
    }
    float* rm = (float*)(smem + SM_RM);      // rm[wn][128 rows]
    if ((lane & 3) == 0) {
        int g = lane >> 2;                   // 0..7
#pragma unroll
        for (int mi = 0; mi < 4; ++mi) {
            int r = wm * 64 + mi * 16 + g;
            rm[wn * 128 + r]     = regmin[mi * 2 + 0];
            rm[wn * 128 + r + 8] = regmin[mi * 2 + 1];
        }
    }
    __syncthreads();

    __shared__ float ws[16];
    float rsum = 0.f;
    if (tid < 128) {
        float v = fminf(fminf(rm[tid], rm[128 + tid]),
                        fminf(rm[256 + tid], rm[384 + tid]));
        rsum = v;
    }
#pragma unroll
    for (int o = 16; o; o >>= 1) {
        rsum += __shfl_xor_sync(0xffffffffu, rsum, o);
        sq   += __shfl_xor_sync(0xffffffffu, sq, o);
    }
    if (lane == 0) { ws[wid] = rsum; ws[8 + wid] = sq; }
    __syncthreads();
    if (tid == 0) {
        atomicAdd(&g_summin, (double)(ws[0] + ws[1] + ws[2] + ws[3]));
        double t = 0.0;
#pragma unroll
        for (int i = 0; i < 8; ++i) t += (double)ws[8 + i];
        atomicAdd(&g_sumx2, t);
    }
}

__global__ void finalize_kernel(float* __restrict__ out, long long loss_idx) {
    double mean = (g_sumx2 + g_summin) / (double)((long long)NVEC * EDIM);
    out[loss_idx] = (float)(1.25 * mean);   // (1 + BETA) * mean
}

extern "C" void kernel_launch(void* const* d_in, const int* in_sizes, int n_in,
                              void* d_out, int out_size) {
    (void)n_in;
    const float* x  = (const float*)d_in[0];
    const float* cb = (const float*)d_in[1];
    float* out = (float*)d_out;

    cudaFuncSetAttribute(vq_mma_kernel, cudaFuncAttributeMaxDynamicSharedMemorySize,
                         SMEM_TOTAL);

    init_kernel<<<1, 1>>>();
    enorm_kernel<<<KCODE, 32>>>(cb);
    cbconv_kernel<<<256, 256>>>(cb);
    vq_mma_kernel<<<NVEC / CTA_M, 256, SMEM_TOTAL>>>(x);

    // out = x (reference returns the rearranged input, which equals x exactly)
    long long ncopy = (long long)in_sizes[0];
    if ((long long)out_size - 1 < ncopy) ncopy = (long long)out_size - 1;
    cudaMemcpyAsync(out, x, (size_t)ncopy * sizeof(float),
                    cudaMemcpyDeviceToDevice);

    finalize_kernel<<<1, 1>>>(out, (long long)out_size - 1);
}

// round 7
// speedup vs baseline: 8.9761x; 1.3355x over previous
#include <cuda_runtime.h>
#include <cuda_bf16.h>
#include <cstdint>

// VectorQuantizer forward (GB300, mma.sync bf16 HMMA):
//   out  = x  (reference returns the rearranged input == x bit-exactly)
//   loss = 1.25/(N*E) * ( sum(x^2) + sum_n min_k( ||e_k||^2 - 2 x_n . e_k ) )
// N=32768, E=256, K=1024.  x: [32,256,32,32] (vector n=(b,hw), dim stride 1024).
// The out-copy is fused into the GEMM kernel's A-build phase (x is read anyway).

#define NVEC  32768
#define EDIM  256
#define KCODE 1024

#define CTA_M 128
#define CTA_N 128             // codes per chunk
#define NCH   (KCODE/CTA_N)   // 8
#define KT    64              // dims per B tile
#define NT    (NCH*(EDIM/KT)) // 32 B tiles total

// smem layout (bytes).  A: 128 rows x 512B, XOR-swizzled (no pad).
#define SM_A   0              // 65536
#define SM_B0  65536          // 16384 (128 codes x 128B, swizzled)
#define SM_B1  81920          // 16384
#define SM_XS  98304          // 8192: f32 stage [16 c][128 hw] (phase 1 only)
#define SM_EN  98304          // 4096  (reuses XS after phase 1)
#define SM_RM  102400         // 2048  (reuses XS tail)
#define SMEM_TOTAL 106496     // x2 CTAs = 212992 <= 228KB/SM

__device__ double g_sumx2;
__device__ double g_summin;
__device__ float  g_enorm2[KCODE];
__device__ __nv_bfloat16 g_cbb[(size_t)KCODE * EDIM];

// ---------------- PTX helpers ----------------
__device__ __forceinline__ uint32_t smem_u32(const void* p) {
    uint32_t a;
    asm("{ .reg .u64 t; cvta.to.shared.u64 t, %1; cvt.u32.u64 %0, t; }"
        : "=r"(a) : "l"(p));
    return a;
}
__device__ __forceinline__ uint32_t pack_bf16x2(float lo, float hi) {
    uint32_t r;
    asm("cvt.rn.bf16x2.f32 %0, %1, %2;" : "=r"(r) : "f"(hi), "f"(lo));
    return r;
}
__device__ __forceinline__ void ldsm_x4(uint32_t* r, uint32_t addr) {
    asm volatile("ldmatrix.sync.aligned.m8n8.x4.shared.b16 {%0,%1,%2,%3}, [%4];"
                 : "=r"(r[0]), "=r"(r[1]), "=r"(r[2]), "=r"(r[3]) : "r"(addr));
}
__device__ __forceinline__ void ldsm_x4t(uint32_t* r, uint32_t addr) {
    asm volatile("ldmatrix.sync.aligned.m8n8.x4.trans.shared.b16 {%0,%1,%2,%3}, [%4];"
                 : "=r"(r[0]), "=r"(r[1]), "=r"(r[2]), "=r"(r[3]) : "r"(addr));
}
__device__ __forceinline__ void mma16816(float* d, const uint32_t* a, const uint32_t* b) {
    asm volatile(
        "mma.sync.aligned.m16n8k16.row.col.f32.bf16.bf16.f32 "
        "{%0,%1,%2,%3}, {%4,%5,%6,%7}, {%8,%9}, {%0,%1,%2,%3};"
        : "+f"(d[0]), "+f"(d[1]), "+f"(d[2]), "+f"(d[3])
        : "r"(a[0]), "r"(a[1]), "r"(a[2]), "r"(a[3]), "r"(b[0]), "r"(b[1]));
}
#define CP_ASYNC16(s, g) \
    asm volatile("cp.async.cg.shared.global [%0], [%1], 16;" :: "r"(s), "l"(g))
#define CP_COMMIT() asm volatile("cp.async.commit_group;" ::: "memory")
#define CP_WAIT1()  asm volatile("cp.async.wait_group 1;" ::: "memory")
#define CP_WAIT0()  asm volatile("cp.async.wait_group 0;" ::: "memory")

// ---------------- prep: init accumulators + codebook bf16 + ||e||^2 ----------------
__global__ void prep_kernel(const float* __restrict__ cb) {
    int k = blockIdx.x, t = threadIdx.x;            // 1024 blocks x 64 threads
    if (k == 0 && t == 0) { g_sumx2 = 0.0; g_summin = 0.0; }
    float4 v = ((const float4*)(cb + (size_t)k * EDIM))[t];
    uint2 p;
    p.x = pack_bf16x2(v.x, v.y);
    p.y = pack_bf16x2(v.z, v.w);
    ((uint2*)(g_cbb + (size_t)k * EDIM))[t] = p;
    float s = v.x * v.x + v.y * v.y + v.z * v.z + v.w * v.w;
#pragma unroll
    for (int o = 16; o; o >>= 1) s += __shfl_xor_sync(0xffffffffu, s, o);
    __shared__ float aa[2];
    if ((t & 31) == 0) aa[t >> 5] = s;
    __syncthreads();
    if (t == 0) g_enorm2[k] = aa[0] + aa[1];
}

// ---------------- fused GEMM + row-min + sum(x^2) + out-copy ----------------
extern __shared__ __align__(1024) unsigned char smem[];

// B tile t: chunk nc=t>>2, k-slice kt=t&3.  128 codes x 64 dims bf16 = 128B/row,
// XOR-swizzled ((row&7)<<4).  4x cp.async.16 per thread.
__device__ __forceinline__ void issueB(uint32_t sb, int tid, int t) {
    uint32_t dstb = sb + ((t & 1) ? SM_B1 : SM_B0);
    const char* gp = (const char*)g_cbb + (size_t)(t >> 2) * (128 * 512)
                   + (size_t)(t & 3) * 128;
#pragma unroll
    for (int s = 0; s < 4; ++s) {
        int i = tid + s * 256;                     // 0..1023
        int r = i >> 3;
        uint32_t c = (uint32_t)(i & 7) * 16;
        CP_ASYNC16(dstb + (uint32_t)r * 128 + (c ^ ((uint32_t)(r & 7) << 4)),
                   gp + (size_t)r * 512 + c);
    }
}

__global__ __launch_bounds__(256, 2) void vq_mma_kernel(const float* __restrict__ x,
                                                        float* __restrict__ out) {
    uint32_t sb = smem_u32(smem);
    int tid = threadIdx.x, lane = tid & 31, wid = tid >> 5;
    int wm = wid >> 2, wn = wid & 3;

    // B tiles 0,1 start loading before phase 1
    issueB(sb, tid, 0); CP_COMMIT();
    issueB(sb, tid, 1); CP_COMMIT();

    // ---- Phase 1: A build (bf16, swizzled) + out copy + sum(x^2) ----
    int n0 = blockIdx.x * CTA_M;
    int b = n0 >> 10, hw0 = n0 & 1023;
    const float* xb = x + (size_t)b * (EDIM * 1024) + hw0;
    float* ob = out + (size_t)b * (EDIM * 1024) + hw0;
    float* xs = (float*)(smem + SM_XS);
    int row = tid & 127, h = tid >> 7;
    uint32_t sxp = (uint32_t)(row & 7) << 4;
    int c0 = tid >> 5, m0 = (tid & 31) * 4;        // stage slot 0
    int c1 = (tid + 256) >> 5, m1 = m0;            // stage slot 1
    float sq = 0.f;
    float4 rv0, rv1;
    rv0 = *(const float4*)(xb + (size_t)c0 * 1024 + m0);
    rv1 = *(const float4*)(xb + (size_t)c1 * 1024 + m1);
#pragma unroll 1
    for (int q = 0; q < 16; ++q) {                 // 16 dims per stage
        *(float4*)(ob + (size_t)(q * 16 + c0) * 1024 + m0) = rv0;
        *(float4*)(ob + (size_t)(q * 16 + c1) * 1024 + m1) = rv1;
        *(float4*)(xs + c0 * 128 + m0) = rv0;
        *(float4*)(xs + c1 * 128 + m1) = rv1;
        __syncthreads();
        if (q < 15) {                              // prefetch next stage (hides DRAM)
            rv0 = *(const float4*)(xb + (size_t)((q + 1) * 16 + c0) * 1024 + m0);
            rv1 = *(const float4*)(xb + (size_t)((q + 1) * 16 + c1) * 1024 + m1);
        }
        float v[8];
#pragma unroll
        for (int m = 0; m < 8; ++m) {
            v[m] = xs[(h * 8 + m) * 128 + row];
            sq += v[m] * v[m];
        }
        uint4 w;
        w.x = pack_bf16x2(v[0], v[1]); w.y = pack_bf16x2(v[2], v[3]);
        w.z = pack_bf16x2(v[4], v[5]); w.w = pack_bf16x2(v[6], v[7]);
        uint32_t col = (uint32_t)(q * 32 + h * 16);
        *(uint4*)(smem + SM_A + row * 512 + (col ^ sxp)) = w;
        __syncthreads();
    }
    // enorm -> smem (reuses XS region; XS dead now)
    {
        float4 e4 = ((const float4*)g_enorm2)[tid];
        *(float4*)(smem + SM_EN + tid * 16) = e4;
    }

    // ---- mainloop ----
    uint32_t sxl = (uint32_t)(lane & 7) << 4;
    uint32_t abase[4];
#pragma unroll
    for (int mi = 0; mi < 4; ++mi)
        abase[mi] = sb + SM_A + (uint32_t)(wm * 64 + mi * 16 + (lane & 15)) * 512;
    uint32_t colA_l = (uint32_t)(lane >> 4) * 16;
    uint32_t brow0  = (uint32_t)(wn * 32 + (lane & 7) + ((lane >> 4) & 1) * 8) * 128;
    uint32_t colB_l = (uint32_t)((lane >> 3) & 1) * 16;

    float regmin[8];
#pragma unroll
    for (int i = 0; i < 8; ++i) regmin[i] = 3.0e38f;

#pragma unroll 1
    for (int nc = 0; nc < NCH; ++nc) {
        float acc[4][4][4];
#pragma unroll
        for (int mi = 0; mi < 4; ++mi)
#pragma unroll
            for (int nj = 0; nj < 4; ++nj)
#pragma unroll
                for (int c = 0; c < 4; ++c) acc[mi][nj][c] = 0.f;

#pragma unroll 1
        for (int kt = 0; kt < 4; ++kt) {
            int t = nc * 4 + kt;
            if (t < NT - 2) CP_WAIT1(); else CP_WAIT0();
            __syncthreads();
            uint32_t bufb = sb + ((t & 1) ? SM_B1 : SM_B0);
#pragma unroll
            for (int kq = 0; kq < 4; ++kq) {
                uint32_t cA = (uint32_t)(kt * 128 + kq * 32) + colA_l;
                uint32_t cB = (uint32_t)(kq * 32) + colB_l;
                uint32_t bf[2][4];
                ldsm_x4t(bf[0], bufb + brow0 + (cB ^ sxl));
                ldsm_x4t(bf[1], bufb + brow0 + 16 * 128 + (cB ^ sxl));
#pragma unroll
                for (int mi = 0; mi < 4; ++mi) {
                    uint32_t af[4];
                    ldsm_x4(af, abase[mi] + (cA ^ sxl));
                    mma16816(acc[mi][0], af, &bf[0][0]);
                    mma16816(acc[mi][1], af, &bf[0][2]);
                    mma16816(acc[mi][2], af, &bf[1][0]);
                    mma16816(acc[mi][3], af, &bf[1][2]);
                }
            }
            __syncthreads();
            if (t + 2 < NT) { issueB(sb, tid, t + 2); CP_COMMIT(); }
        }
        // epilogue: fold en[k] - 2*dot into per-lane row minima
        const float* en = (const float*)(smem + SM_EN) + nc * 128;
#pragma unroll
        for (int nj = 0; nj < 4; ++nj) {
            int col = wn * 32 + nj * 8 + (lane & 3) * 2;
            float e0 = en[col], e1 = en[col + 1];
#pragma unroll
            for (int mi = 0; mi < 4; ++mi) {
                float s0 = fmaf(acc[mi][nj][0], -2.f, e0);
                float s1 = fmaf(acc[mi][nj][1], -2.f, e1);
                float s2 = fmaf(acc[mi][nj][2], -2.f, e0);
                float s3 = fmaf(acc[mi][nj][3], -2.f, e1);
                regmin[mi * 2 + 0] = fminf(regmin[mi * 2 + 0], fminf(s0, s1));
                regmin[mi * 2 + 1] = fminf(regmin[mi * 2 + 1], fminf(s2, s3));
            }
        }
    }

    // ---- reductions ----
#pragma unroll
    for (int i = 0; i < 8; ++i) {
        regmin[i] = fminf(regmin[i], __shfl_xor_sync(0xffffffffu, regmin[i], 1));
        regmin[i] = fminf(regmin[i], __shfl_xor_sync(0xffffffffu, regmin[i], 2));
    }
    float* rm = (float*)(smem + SM_RM);            // rm[wn][128]
    __syncthreads();                               // en reads done before overwrite
    if ((lane & 3) == 0) {
        int g = lane >> 2;
#pragma unroll
        for (int mi = 0; mi < 4; ++mi) {
            int r = wm * 64 + mi * 16 + g;
            rm[wn * 128 + r]     = regmin[mi * 2 + 0];
            rm[wn * 128 + r + 8] = regmin[mi * 2 + 1];
        }
    }
    __syncthreads();

    __shared__ float ws[16];
    float rsum = 0.f;
    if (tid < 128)
        rsum = fminf(fminf(rm[tid], rm[128 + tid]),
                     fminf(rm[256 + tid], rm[384 + tid]));
#pragma unroll
    for (int o = 16; o; o >>= 1) {
        rsum += __shfl_xor_sync(0xffffffffu, rsum, o);
        sq   += __shfl_xor_sync(0xffffffffu, sq, o);
    }
    if (lane == 0) { ws[wid] = rsum; ws[8 + wid] = sq; }
    __syncthreads();
    if (tid == 0) {
        atomicAdd(&g_summin, (double)(ws[0] + ws[1] + ws[2] + ws[3]));
        double t = 0.0;
#pragma unroll
        for (int i = 0; i < 8; ++i) t += (double)ws[8 + i];
        atomicAdd(&g_sumx2, t);
    }
}

__global__ void finalize_kernel(float* __restrict__ out, long long loss_idx) {
    double mean = (g_sumx2 + g_summin) / (double)((long long)NVEC * EDIM);
    out[loss_idx] = (float)(1.25 * mean);          // (1 + BETA) * mean
}

extern "C" void kernel_launch(void* const* d_in, const int* in_sizes, int n_in,
                              void* d_out, int out_size) {
    (void)n_in; (void)in_sizes;
    const float* x  = (const float*)d_in[0];
    const float* cb = (const float*)d_in[1];
    float* out = (float*)d_out;

    cudaFuncSetAttribute(vq_mma_kernel, cudaFuncAttributeMaxDynamicSharedMemorySize,
                         SMEM_TOTAL);

    prep_kernel<<<KCODE, 64>>>(cb);
    vq_mma_kernel<<<NVEC / CTA_M, 256, SMEM_TOTAL>>>(x, out);
    finalize_kernel<<<1, 1>>>(out, (long long)out_size - 1);
}